// round 8
// baseline (speedup 1.0000x reference)
#include <cuda_runtime.h>

// Problem constants (fixed by the reference):
//   N=4096 samples, D=128 input dim, P=128 pe dim (== D), H=256 hidden.
#define NN 4096
#define DD 128
#define HH 256

// Scratch: base[n][h] = (x @ W1[:D])[n][h] + b1[h]
__device__ float g_base[NN * HH];

typedef unsigned long long u64;

__device__ __forceinline__ u64 pk2(float x, float y) {
    u64 r; asm("mov.b64 %0, {%1, %2};" : "=l"(r) : "f"(x), "f"(y)); return r;
}
__device__ __forceinline__ u64 fma2_(u64 a, u64 b, u64 c) {
    u64 d; asm("fma.rn.f32x2 %0, %1, %2, %3;" : "=l"(d) : "l"(a), "l"(b), "l"(c)); return d;
}
__device__ __forceinline__ u64 add2_(u64 a, u64 b) {
    u64 d; asm("add.rn.f32x2 %0, %1, %2;" : "=l"(d) : "l"(a), "l"(b)); return d;
}
__device__ __forceinline__ u64 relu2_(u64 a) {
    float x, y;
    asm("mov.b64 {%0, %1}, %2;" : "=f"(x), "=f"(y) : "l"(a));
    x = fmaxf(x, 0.0f); y = fmaxf(y, 0.0f);
    return pk2(x, y);
}
__device__ __forceinline__ float2 unpk(u64 a) {
    float2 v; asm("mov.b64 {%0, %1}, %2;" : "=f"(v.x), "=f"(v.y) : "l"(a)); return v;
}

// ---------------------------------------------------------------------------
// K1: base = x @ W1[:D] + b1   (4096 x 256, K=128), f32x2 accumulators.
// ---------------------------------------------------------------------------
__global__ __launch_bounds__(256) void nimo_base_kernel(
    const float* __restrict__ x, const float* __restrict__ W1,
    const float* __restrict__ b1, float* __restrict__ out)
{
    __shared__ __align__(16) float xs[32][68];
    __shared__ __align__(16) float ws[32][68];

    const int tid = threadIdx.x;
    const int n0 = blockIdx.x * 64;
    const int h0 = blockIdx.y * 64;
    const int tx = tid & 15;
    const int ty = tid >> 4;

    u64 acc[4][2];
#pragma unroll
    for (int i = 0; i < 4; i++) { acc[i][0] = 0ull; acc[i][1] = 0ull; }

    for (int kt = 0; kt < DD; kt += 32) {
#pragma unroll
        for (int i = 0; i < 8; i++) {
            int e = tid + i * 256;
            int r = e >> 5, k = e & 31;
            xs[k][r] = x[(n0 + r) * DD + kt + k];
        }
#pragma unroll
        for (int i = 0; i < 8; i++) {
            int e = tid + i * 256;
            int k = e >> 6, c = e & 63;
            ws[k][c] = W1[(kt + k) * HH + h0 + c];
        }
        __syncthreads();
#pragma unroll
        for (int kk = 0; kk < 32; kk++) {
            float4 xv = *(const float4*)&xs[kk][ty * 4];
            float4 wv = *(const float4*)&ws[kk][tx * 4];
            u64 wa = pk2(wv.x, wv.y), wb = pk2(wv.z, wv.w);
            u64 x0 = pk2(xv.x, xv.x), x1 = pk2(xv.y, xv.y);
            u64 x2 = pk2(xv.z, xv.z), x3 = pk2(xv.w, xv.w);
            acc[0][0] = fma2_(x0, wa, acc[0][0]); acc[0][1] = fma2_(x0, wb, acc[0][1]);
            acc[1][0] = fma2_(x1, wa, acc[1][0]); acc[1][1] = fma2_(x1, wb, acc[1][1]);
            acc[2][0] = fma2_(x2, wa, acc[2][0]); acc[2][1] = fma2_(x2, wb, acc[2][1]);
            acc[3][0] = fma2_(x3, wa, acc[3][0]); acc[3][1] = fma2_(x3, wb, acc[3][1]);
        }
        __syncthreads();
    }

    float4 bv = *(const float4*)&b1[h0 + tx * 4];
    u64 ba = pk2(bv.x, bv.y), bb = pk2(bv.z, bv.w);
#pragma unroll
    for (int i = 0; i < 4; i++) {
        float2 oa = unpk(add2_(acc[i][0], ba));
        float2 ob = unpk(add2_(acc[i][1], bb));
        float4 o = make_float4(oa.x, oa.y, ob.x, ob.y);
        *(float4*)&g_base[(n0 + ty * 4 + i) * HH + h0 + tx * 4] = o;
    }

    if (blockIdx.y == 0 && tid < 64) out[(n0 + tid) * (DD + 1)] = 1.0f;
}

// ---------------------------------------------------------------------------
// K2: software-pipelined masked-MLP evaluation (see theory above).
// ---------------------------------------------------------------------------
__global__ __launch_bounds__(128, 4) void nimo_main_kernel(
    const float* __restrict__ x, const float* __restrict__ W1,
    const float* __restrict__ W2, const float* __restrict__ b2,
    float* __restrict__ out)
{
    __shared__ __align__(8) float2 xs2[32][33];   // (-x, -x) per (n', j')

    const int tid  = threadIdx.x;
    const int lane = tid & 31;
    const int warp = tid >> 5;
    const int n0   = blockIdx.x * 32;
    const int j0   = blockIdx.y * 32;
    const int nb   = n0 + warp * 8;

#pragma unroll
    for (int i = 0; i < 8; i++) {
        int e = tid + i * 128;
        int r = e >> 5, c = e & 31;
        float v = x[(n0 + r) * DD + j0 + c];
        xs2[r][c] = make_float2(-v, -v);
    }

    u64 bp[8][4], w2p[4];
    {
        const float4* w2r = (const float4*)W2;
        float4 wa = w2r[lane], wb = w2r[32 + lane];
        w2p[0] = pk2(wa.x, wa.y); w2p[1] = pk2(wa.z, wa.w);
        w2p[2] = pk2(wb.x, wb.y); w2p[3] = pk2(wb.z, wb.w);
#pragma unroll
        for (int i = 0; i < 8; i++) {
            const float4* br = (const float4*)&g_base[(nb + i) * HH];
            float4 ba = br[lane], bb = br[32 + lane];
            bp[i][0] = pk2(ba.x, ba.y); bp[i][1] = pk2(ba.z, ba.w);
            bp[i][2] = pk2(bb.x, bb.y); bp[i][3] = pk2(bb.z, bb.w);
        }
    }
    const float ob2 = 1.0f + b2[0];
    const bool h16 = (lane & 16) != 0;
    const bool h8  = (lane & 8) != 0;
    const bool h4  = (lane & 4) != 0;

    __syncthreads();

    float4 fwa, fwb;
    {
        const float4* w1r = (const float4*)&W1[j0 * HH];
        fwa = w1r[lane]; fwb = w1r[32 + lane];
    }

    auto MATH = [&](int jj, float* r) {
        const int j = j0 + jj;
        const float4* per = (const float4*)&W1[(DD + j) * HH];
        float4 pa = per[lane], pb = per[32 + lane];
        u64 w1p0 = pk2(fwa.x, fwa.y), w1p1 = pk2(fwa.z, fwa.w);
        u64 w1p2 = pk2(fwb.x, fwb.y), w1p3 = pk2(fwb.z, fwb.w);
        if (jj < 31) {
            const float4* nw = (const float4*)&W1[(j + 1) * HH];
            fwa = nw[lane]; fwb = nw[32 + lane];
        }
        u64 pep0 = pk2(pa.x, pa.y), pep1 = pk2(pa.z, pa.w);
        u64 pep2 = pk2(pb.x, pb.y), pep3 = pk2(pb.z, pb.w);

        float s[8];
#pragma unroll
        for (int i = 0; i < 8; i++) {
            const u64 nx2 = *(const u64*)&xs2[warp * 8 + i][jj];  // (-xj,-xj)
            u64 a0, a1;
            a0 = fma2_(relu2_(add2_(fma2_(nx2, w1p0, pep0), bp[i][0])), w2p[0], 0ull);
            a1 = fma2_(relu2_(add2_(fma2_(nx2, w1p1, pep1), bp[i][1])), w2p[1], 0ull);
            a0 = fma2_(relu2_(add2_(fma2_(nx2, w1p2, pep2), bp[i][2])), w2p[2], a0);
            a1 = fma2_(relu2_(add2_(fma2_(nx2, w1p3, pep3), bp[i][3])), w2p[3], a1);
            float2 t = unpk(add2_(a0, a1));
            s[i] = t.x + t.y;
        }
#pragma unroll
        for (int k = 0; k < 4; k++) {
            float snd = h16 ? s[k] : s[k + 4];
            float kp  = h16 ? s[k + 4] : s[k];
            r[k] = kp + __shfl_xor_sync(0xffffffffu, snd, 16);
        }
    };

    auto REDUCE = [&](float* r, int jj) {
        const int j = j0 + jj;
        float t0, t1;
        {
            float snd = h8 ? r[0] : r[2];
            float kp  = h8 ? r[2] : r[0];
            t0 = kp + __shfl_xor_sync(0xffffffffu, snd, 8);
            snd = h8 ? r[1] : r[3];
            kp  = h8 ? r[3] : r[1];
            t1 = kp + __shfl_xor_sync(0xffffffffu, snd, 8);
        }
        {
            float snd = h4 ? t0 : t1;
            float kp  = h4 ? t1 : t0;
            t0 = kp + __shfl_xor_sync(0xffffffffu, snd, 4);
        }
        t0 += __shfl_xor_sync(0xffffffffu, t0, 2);
        t0 += __shfl_xor_sync(0xffffffffu, t0, 1);
        if ((lane & 3) == 0) {
            const int v = lane >> 2;
            const float nxj = xs2[warp * 8 + v][jj].x;   // = -xj
            out[(nb + v) * (DD + 1) + 1 + j] = -(nxj * (ob2 + t0));
        }
    };

    // Pipelined loop. Trace (jj = 1,3,...,31):
    //   jj=1 : MATH(1,rB) REDUCE(rA,0) MATH(2,rA) REDUCE(rB,1)
    //   ...
    //   jj=31: MATH(31,rB) REDUCE(rA,30) [guard skips MATH(32)] REDUCE(rB,31)
    // Every column 0..31 is reduced exactly once.
    float rA[4], rB[4];
    MATH(0, rA);
#pragma unroll 1
    for (int jj = 1; jj < 32; jj += 2) {
        MATH(jj, rB);
        REDUCE(rA, jj - 1);
        if (jj + 1 < 32) MATH(jj + 1, rA);
        REDUCE(rB, jj);
    }
}

extern "C" void kernel_launch(void* const* d_in, const int* in_sizes, int n_in,
                              void* d_out, int out_size)
{
    const float* x  = (const float*)d_in[0];
    const float* W1 = (const float*)d_in[1];
    const float* b1 = (const float*)d_in[2];
    const float* W2 = (const float*)d_in[3];
    const float* b2 = (const float*)d_in[4];
    float* out = (float*)d_out;

    nimo_base_kernel<<<dim3(64, 4), 256>>>(x, W1, b1, out);
    nimo_main_kernel<<<dim3(128, 4), 128>>>(x, W1, W2, b2, out);
}